// round 8
// baseline (speedup 1.0000x reference)
#include <cuda_runtime.h>

// BaseGraphPooling: segment-mean over sorted node_batch.
// node_h: [N,128] fp32, node_batch: [N] int32 sorted, out: [G,128] fp32.
//
// SINGLE fused kernel, self-cleaning device scratch:
//  - 1184 CTAs (148 SMs x 8, guaranteed co-resident by __launch_bounds__(256,8))
//    each own a fixed contiguous row chunk -> perfect per-SM byte balance.
//  - CTA's index slice staged to smem in one coalesced burst; sub-segment
//    boundaries via smem binary search. Partial sums -> red.global.add.v4.f32
//    into g_scratch; lengths -> int atomic into g_count.
//  - Software grid barrier (safe: one wave): all CTAs arrive; CTAs 0..127
//    spin, then cooperatively divide by count, write d_out, and re-zero
//    scratch + counters for the next graph replay.

#define NUM_CTAS 1184       // 148 SMs * 8 CTAs/SM, exactly one wave
#define EPI_CTAS 128        // epilogue CTAs: 128 * 256 threads = 1024 graphs * 32 lanes
#define MAX_G    1024
#define MAX_RPC  1728       // max rows_per_cta supported by smem staging

__device__ float4       g_scratch[MAX_G * 32];  // zero-initialized at load
__device__ int          g_count[MAX_G];         // zero-initialized at load
__device__ unsigned int g_arrive = 0;           // grid-barrier arrival counter
__device__ unsigned int g_epi_done = 0;         // epilogue completion counter

__device__ __forceinline__ float4 f4add(float4 a, float4 b) {
    a.x += b.x; a.y += b.y; a.z += b.z; a.w += b.w; return a;
}

__device__ __forceinline__ void red_add_v4(float4* addr, float4 v) {
    asm volatile("red.global.add.v4.f32 [%0], {%1, %2, %3, %4};"
                 :: "l"(addr), "f"(v.x), "f"(v.y), "f"(v.z), "f"(v.w)
                 : "memory");
}

__device__ __forceinline__ void red_add_s32(int* addr, int v) {
    asm volatile("red.global.add.s32 [%0], %1;" :: "l"(addr), "r"(v) : "memory");
}

__global__ __launch_bounds__(256, 8)
void fused_segment_mean_kernel(const float4* __restrict__ h,    // N*32 float4
                               const int* __restrict__ batch,   // N int32, sorted
                               float4* __restrict__ out,        // G*32 float4
                               int N, int G, int rows_per_cta) {
    const int tid = threadIdx.x;
    const int c   = tid & 31;   // float4 column (0..31)
    const int r   = tid >> 5;   // row phase (0..7)
    const int bid = blockIdx.x;

    __shared__ float4 smem[256];
    __shared__ int    sb[MAX_RPC];

    const int c0 = bid * rows_per_cta;
    const int c1 = min(c0 + rows_per_cta, N);

    if (c0 < c1) {
        const int len = c1 - c0;
        // Stage this CTA's index slice into smem (coalesced, high-MLP burst).
        for (int i = tid; i < len; i += 256)
            sb[i] = batch[c0 + i];
        __syncthreads();

        int s = c0;
        while (s < c1) {
            const int g = sb[s - c0];           // current segment id (uniform)
            // upper_bound(g) within [s, c1) via smem binary search (~11 LDS)
            int lo = s, hi = c1;
            while (lo < hi) {
                int mid = (lo + hi) >> 1;
                if (sb[mid - c0] <= g) lo = mid + 1; else hi = mid;
            }
            const int e = lo;

            float4 a0 = make_float4(0.f, 0.f, 0.f, 0.f);
            float4 a1 = a0, a2 = a0, a3 = a0;

            int i = s + r;
            for (; i + 24 < e; i += 32) {
                float4 v0 = __ldcs(&h[(size_t)(i     ) * 32 + c]);
                float4 v1 = __ldcs(&h[(size_t)(i +  8) * 32 + c]);
                float4 v2 = __ldcs(&h[(size_t)(i + 16) * 32 + c]);
                float4 v3 = __ldcs(&h[(size_t)(i + 24) * 32 + c]);
                a0 = f4add(a0, v0);
                a1 = f4add(a1, v1);
                a2 = f4add(a2, v2);
                a3 = f4add(a3, v3);
            }
            for (; i < e; i += 8)
                a0 = f4add(a0, __ldcs(&h[(size_t)i * 32 + c]));

            smem[tid] = f4add(f4add(a0, a1), f4add(a2, a3));
            __syncthreads();

            if (tid == 0)
                red_add_s32(&g_count[g], e - s);
            if (r == 0) {
                float4 acc = smem[c];
                #pragma unroll
                for (int p = 1; p < 8; p++)
                    acc = f4add(acc, smem[p * 32 + c]);
                red_add_v4(&g_scratch[(size_t)g * 32 + c], acc);
            }
            __syncthreads();   // smem reuse safety for next sub-segment

            s = e;
        }
    }

    // ---- grid barrier arrival (release) ----
    __syncthreads();
    if (tid == 0) {
        __threadfence();                   // make red.adds visible gpu-wide
        atomicAdd(&g_arrive, 1u);
    }

    if (bid >= EPI_CTAS) return;           // non-epilogue CTAs exit

    // ---- epilogue CTAs: wait for all arrivals (acquire) ----
    if (tid == 0) {
        while (atomicAdd(&g_arrive, 0u) < (unsigned)NUM_CTAS)
            __nanosleep(64);
        __threadfence();
    }
    __syncthreads();

    // 8 graphs per CTA: thread -> (graph, column)
    const int idx = bid * 256 + tid;
    const int g   = idx >> 5;
    const int cc  = idx & 31;
    if (g < G) {
        const int cnt = g_count[g];
        const float inv = 1.0f / (float)max(cnt, 1);
        float4 v = g_scratch[(size_t)g * 32 + cc];
        g_scratch[(size_t)g * 32 + cc] = make_float4(0.f, 0.f, 0.f, 0.f);
        if (cc == 0) g_count[g] = 0;
        v.x *= inv; v.y *= inv; v.z *= inv; v.w *= inv;
        out[(size_t)g * 32 + cc] = v;
    }

    // ---- reset barrier counters for next graph replay ----
    __syncthreads();
    if (tid == 0) {
        unsigned done = atomicAdd(&g_epi_done, 1u);
        if (done == EPI_CTAS - 1) {        // last epilogue CTA cleans up
            g_arrive   = 0;
            g_epi_done = 0;
            __threadfence();
        }
    }
}

extern "C" void kernel_launch(void* const* d_in, const int* in_sizes, int n_in,
                              void* d_out, int out_size) {
    const float4* h     = (const float4*)d_in[0];
    const int*    batch = (const int*)d_in[1];
    const int N = in_sizes[1];       // number of nodes
    const int G = out_size / 128;    // number of graphs

    int rows_per_cta = (N + NUM_CTAS - 1) / NUM_CTAS;
    fused_segment_mean_kernel<<<NUM_CTAS, 256>>>(h, batch, (float4*)d_out,
                                                 N, G, rows_per_cta);
}